// round 4
// baseline (speedup 1.0000x reference)
#include <cuda_runtime.h>
#include <cstdint>

// x: [64,1,512,512] f32; kernels: [5,1,3,3]; biases: [5]
// conv VALID -> [64,5,510,510]; +bias; maxpool2x2 -> [64,5,255,255]; relu.
//
// Strategy: FMA-pipe bound kernel (measured). Use packed fp32x2 FMA
// (fma.rn.f32x2, 2 FMAs/instr) by having each thread compute TWO pooled
// outputs: (pw, pw+32). Shared input tile is stored PRE-PAIRED:
//   sP[r][c] = { in[r][c], in[r][c+64] }
// so every packed conv operand is one aligned LDS.64 — no register packing.
// Weights/bias duplicated {w,w} in shared for free broadcast operands.

#define TX 32
#define TY 8
#define NTHR (TX * TY)         // 256
#define OUTW 64                // pooled cols per block (2 per thread-x)
#define INW 512
#define POW 255
#define IH 18                  // 2*TY + 2 input rows per tile
#define PCOLS 66               // pair columns needed: c in 0..65
#define ICOLS 130              // raw input cols per tile: 0..129
#define IC2 65                 // float2 loads per row

__device__ __forceinline__ void ffma2(uint64_t& d, uint64_t a, uint64_t b, uint64_t c) {
    asm("fma.rn.f32x2 %0, %1, %2, %3;" : "=l"(d) : "l"(a), "l"(b), "l"(c));
}
__device__ __forceinline__ void unpack2(float& lo, float& hi, uint64_t v) {
    asm("mov.b64 {%0, %1}, %2;" : "=f"(lo), "=f"(hi) : "l"(v));
}

__global__ __launch_bounds__(NTHR)
void fused_conv_bias_pool_relu(const float* __restrict__ x,
                               const float* __restrict__ w,
                               const float* __restrict__ b,
                               float* __restrict__ out)
{
    __shared__ float2 sP[IH][PCOLS];   // paired input tile: {c, c+64}
    __shared__ float2 sW2[5][9];       // duplicated weights {w,w}
    __shared__ float2 sB2[5];          // duplicated bias

    const int n   = blockIdx.z;
    const int pw0 = blockIdx.x * OUTW;        // pooled col base (0,64,128,192)
    const int ph0 = blockIdx.y * TY;
    const int tx  = threadIdx.x;
    const int ty  = threadIdx.y;
    const int tid = ty * TX + tx;

    if (tid < 45)      { float v = w[tid]; sW2[tid / 9][tid % 9] = make_float2(v, v); }
    else if (tid < 50) { float v = b[tid - 45]; sB2[tid - 45] = make_float2(v, v); }

    // Cooperative load of the 130x18 raw tile, written in paired layout.
    // Raw col c (block-relative) lands in sP[r][c].x (c<=65) and
    // sP[r][c-64].y (c>=64).
    const float* __restrict__ xn = x + (size_t)n * INW * INW;
    const int ix0 = 2 * pw0;                  // 0,128,256,384 (even)
    const int iy0 = 2 * ph0;
    for (int i = tid; i < IH * IC2; i += NTHR) {
        const int r  = i / IC2;
        const int c2 = i - r * IC2;
        const int gy = iy0 + r;
        const int gx = ix0 + 2 * c2;
        float2 v;
        if (gy < INW && gx + 1 < INW) {
            v = *reinterpret_cast<const float2*>(xn + (size_t)gy * INW + gx);
        } else {
            v.x = (gy < INW && gx < INW) ? xn[(size_t)gy * INW + gx] : 0.0f;
            v.y = 0.0f;
        }
        const int c0 = 2 * c2, c1 = 2 * c2 + 1;
        if (c0 < PCOLS)  sP[r][c0].x = v.x;
        if (c1 < PCOLS)  sP[r][c1].x = v.y;
        if (c0 >= 64)    sP[r][c0 - 64].y = v.x;
        if (c1 >= 64)    sP[r][c1 - 64].y = v.y;
    }
    __syncthreads();

    const int ph = ph0 + ty;
    if (ph >= POW) return;                    // only last by-row partially masked
    const int pw_a = pw0 + tx;                // always < 255 (max 223)
    const int pw_b = pw_a + 32;               // may be 255 -> masked
    const bool bval = (pw_b < POW);

    // Packed 4x4 patch: pp[r][j] = { in[2ph+r][2pw_a+j], in[..][2pw_b+j] }
    uint64_t pp[4][4];
    #pragma unroll
    for (int r = 0; r < 4; r++) {
        const uint64_t* row = reinterpret_cast<const uint64_t*>(&sP[2 * ty + r][2 * tx]);
        #pragma unroll
        for (int j = 0; j < 4; j++) pp[r][j] = row[j];
    }

    const size_t cstride = (size_t)POW * POW;
    size_t obase = (((size_t)n * 5) * POW + ph) * POW + pw_a;
    const uint64_t* wp = reinterpret_cast<const uint64_t*>(&sW2[0][0]);
    const uint64_t* bp = reinterpret_cast<const uint64_t*>(&sB2[0]);

    #pragma unroll
    for (int ch = 0; ch < 5; ch++) {
        uint64_t kk[9];
        #pragma unroll
        for (int i = 0; i < 9; i++) kk[i] = wp[ch * 9 + i];
        const uint64_t bias2 = bp[ch];

        uint64_t A[4];
        #pragma unroll
        for (int dy = 0; dy < 2; dy++)
            #pragma unroll
            for (int dx = 0; dx < 2; dx++) {
                uint64_t acc = bias2;
                #pragma unroll
                for (int ky = 0; ky < 3; ky++)
                    #pragma unroll
                    for (int kx = 0; kx < 3; kx++)
                        ffma2(acc, pp[dy + ky][dx + kx], kk[ky * 3 + kx], acc);
                A[dy * 2 + dx] = acc;
            }

        float l0, h0, l1, h1, l2, h2, l3, h3;
        unpack2(l0, h0, A[0]);
        unpack2(l1, h1, A[1]);
        unpack2(l2, h2, A[2]);
        unpack2(l3, h3, A[3]);
        const float ma = fmaxf(fmaxf(fmaxf(l0, l1), fmaxf(l2, l3)), 0.0f);
        const float mb = fmaxf(fmaxf(fmaxf(h0, h1), fmaxf(h2, h3)), 0.0f);

        out[obase] = ma;
        if (bval) out[obase + 32] = mb;
        obase += cstride;
    }
}

extern "C" void kernel_launch(void* const* d_in, const int* in_sizes, int n_in,
                              void* d_out, int out_size)
{
    const float* x = (const float*)d_in[0];
    const float* w = (const float*)d_in[1];
    const float* b = (const float*)d_in[2];
    float* out = (float*)d_out;

    dim3 block(TX, TY, 1);                       // 256 threads
    dim3 grid((POW + OUTW - 1) / OUTW,           // 4
              (POW + TY - 1) / TY,               // 32
              64);                               // batch
    fused_conv_bias_pool_relu<<<grid, block>>>(x, w, b, out);
}

// round 5
// speedup vs baseline: 1.2051x; 1.2051x over previous
#include <cuda_runtime.h>
#include <cstdint>

// x: [64,1,512,512] f32; kernels: [5,1,3,3]; biases: [5]
// conv VALID -> [64,5,510,510]; +bias; maxpool2x2 -> [64,5,255,255]; relu.
//
// Measured (R3/R4): kernel is FFMA-issue/latency bound. Scalar FFMA floor
// ~= 40-44us chip-wide. This version: each thread computes TWO vertically
// adjacent pooled outputs from a 6x4 register patch -> 8 independent 9-FMA
// chains per channel (ILP), weights/indexing amortized 2x.

#define TX 32
#define TY 8
#define NTHR (TX * TY)        // 256
#define PR_PER_BLOCK 16       // pooled rows per block (2 per thread-y)
#define INW 512
#define POW 255
#define TILE_H 34             // 2*16 + 2 input rows
#define TILE_W 66             // 2*32 + 2 input cols
#define TILE_W2 33            // float2 per row
#define NLD (TILE_H * TILE_W2) // 1122 float2 loads per tile

__global__ __launch_bounds__(NTHR, 4)
void fused_conv_bias_pool_relu(const float* __restrict__ x,
                               const float* __restrict__ w,
                               const float* __restrict__ b,
                               float* __restrict__ out)
{
    __shared__ float sIn[TILE_H][TILE_W];
    __shared__ float sW[5][9];
    __shared__ float sB[5];

    const int n   = blockIdx.z;
    const int pw0 = blockIdx.x * TX;              // pooled col base
    const int ph0 = blockIdx.y * PR_PER_BLOCK;    // pooled row base
    const int tx  = threadIdx.x;
    const int ty  = threadIdx.y;
    const int tid = ty * TX + tx;

    if (tid < 45)      sW[tid / 9][tid % 9] = w[tid];
    else if (tid < 50) sB[tid - 45] = b[tid - 45];

    // Cooperative float2 load of the 66x34 input tile (clamp -> 0 pad).
    const float* __restrict__ xn = x + (size_t)n * INW * INW;
    const int ix0 = 2 * pw0;                      // even
    const int iy0 = 2 * ph0;
    #pragma unroll 5
    for (int i = tid; i < NLD; i += NTHR) {
        const int r  = i / TILE_W2;
        const int c2 = i - r * TILE_W2;
        const int gy = iy0 + r;
        const int gx = ix0 + 2 * c2;
        float2 v;
        if (gy < INW && gx + 1 < INW) {
            v = *reinterpret_cast<const float2*>(xn + (size_t)gy * INW + gx);
        } else {
            v.x = (gy < INW && gx < INW) ? xn[(size_t)gy * INW + gx] : 0.0f;
            v.y = 0.0f;
        }
        sIn[r][2 * c2]     = v.x;
        sIn[r][2 * c2 + 1] = v.y;
    }
    __syncthreads();

    const int pw  = pw0 + tx;          // col for both outputs
    const int pr0 = ph0 + 2 * ty;      // first pooled row
    const int pr1 = pr0 + 1;           // second pooled row
    if (pw >= POW || pr0 >= POW) return;
    const bool r1ok = (pr1 < POW);

    // 6x4 register patch (rows 4ty..4ty+5, cols 2tx..2tx+3), via LDS.64.
    float p[6][4];
    #pragma unroll
    for (int r = 0; r < 6; r++) {
        const float2* row = reinterpret_cast<const float2*>(
            &sIn[4 * ty + r][2 * tx]);
        float2 a = row[0];
        float2 c = row[1];
        p[r][0] = a.x; p[r][1] = a.y; p[r][2] = c.x; p[r][3] = c.y;
    }

    const size_t cstride = (size_t)POW * POW;
    size_t o0 = (((size_t)n * 5) * POW + pr0) * POW + pw;

    #pragma unroll
    for (int ch = 0; ch < 5; ch++) {
        float k[9];
        #pragma unroll
        for (int i = 0; i < 9; i++) k[i] = sW[ch][i];
        const float bias = sB[ch];

        // 8 independent accumulator chains: 2 outputs x 4 conv positions.
        float acc[2][4];
        #pragma unroll
        for (int o = 0; o < 2; o++)
            #pragma unroll
            for (int j = 0; j < 4; j++) acc[o][j] = bias;

        #pragma unroll
        for (int ky = 0; ky < 3; ky++)
            #pragma unroll
            for (int kx = 0; kx < 3; kx++) {
                const float kv = k[ky * 3 + kx];
                #pragma unroll
                for (int o = 0; o < 2; o++)
                    #pragma unroll
                    for (int dy = 0; dy < 2; dy++)
                        #pragma unroll
                        for (int dx = 0; dx < 2; dx++)
                            acc[o][dy * 2 + dx] =
                                fmaf(p[2 * o + dy + ky][dx + kx], kv,
                                     acc[o][dy * 2 + dx]);
            }

        const float m0 = fmaxf(fmaxf(fmaxf(acc[0][0], acc[0][1]),
                                     fmaxf(acc[0][2], acc[0][3])), 0.0f);
        const float m1 = fmaxf(fmaxf(fmaxf(acc[1][0], acc[1][1]),
                                     fmaxf(acc[1][2], acc[1][3])), 0.0f);
        out[o0] = m0;
        if (r1ok) out[o0 + POW] = m1;
        o0 += cstride;
    }
}

extern "C" void kernel_launch(void* const* d_in, const int* in_sizes, int n_in,
                              void* d_out, int out_size)
{
    const float* x = (const float*)d_in[0];
    const float* w = (const float*)d_in[1];
    const float* b = (const float*)d_in[2];
    float* out = (float*)d_out;

    dim3 block(TX, TY, 1);                             // 256 threads
    dim3 grid((POW + TX - 1) / TX,                     // 8
              (POW + PR_PER_BLOCK - 1) / PR_PER_BLOCK, // 16
              64);                                     // batch
    fused_conv_bias_pool_relu<<<grid, block>>>(x, w, b, out);
}

// round 7
// speedup vs baseline: 1.6730x; 1.3882x over previous
#include <cuda_runtime.h>
#include <cstdint>

// x: [64,1,512,512] f32; kernels: [5,1,3,3]; biases: [5]
// conv VALID -> [64,5,510,510]; +bias; maxpool2x2 -> [64,5,255,255]; relu.
//
// Measured model (R3-R5): issue-slot bound, dur ~ warp_instrs/(592*issue_eff).
// This round: raise occupancy (36-reg cap -> 56 warps/SM) and expose ILP=4
// in the conv accumulation. One pooled output per thread (R3 layout).

#define TX 32
#define TY 8
#define NTHR (TX * TY)
#define IW 66              // 2*TX + 2 tile floats per row
#define IW2 33             // float2 per tile row
#define IH 18              // 2*TY + 2
#define INW 512
#define POW 255
#define NLD (IH * IW2)     // 594

__device__ __forceinline__ void load_tile_elem(const float* __restrict__ xn,
                                               float (*sIn)[IW],
                                               int i, int iy0, int ix0)
{
    const int r  = i / IW2;
    const int c2 = i - r * IW2;
    const int gy = iy0 + r;
    const int gx = ix0 + 2 * c2;
    float2 v;
    if (gy < INW && gx + 1 < INW) {
        v = *reinterpret_cast<const float2*>(xn + (size_t)gy * INW + gx);
    } else {
        v.x = (gy < INW && gx < INW) ? xn[(size_t)gy * INW + gx] : 0.0f;
        v.y = 0.0f;
    }
    sIn[r][2 * c2]     = v.x;
    sIn[r][2 * c2 + 1] = v.y;
}

__global__ __launch_bounds__(NTHR, 7)
void fused_conv_bias_pool_relu(const float* __restrict__ x,
                               const float* __restrict__ w,
                               const float* __restrict__ b,
                               float* __restrict__ out)
{
    __shared__ float sIn[IH][IW];
    __shared__ float sW[5][9];
    __shared__ float sB[5];

    const int n   = blockIdx.z;
    const int pw0 = blockIdx.x * TX;
    const int ph0 = blockIdx.y * TY;
    const int tx  = threadIdx.x;
    const int ty  = threadIdx.y;
    const int tid = ty * TX + tx;

    if (tid < 45)      sW[tid / 9][tid % 9] = w[tid];
    else if (tid < 50) sB[tid - 45] = b[tid - 45];

    // Cooperative float2 load of the 66x18 tile (clamp -> 0 pad).
    // 594 loads / 256 threads: 2 unconditional + 1 masked (peeled for MLP).
    const float* __restrict__ xn = x + (size_t)n * INW * INW;
    const int ix0 = 2 * pw0;               // even
    const int iy0 = 2 * ph0;
    load_tile_elem(xn, sIn, tid,          iy0, ix0);
    load_tile_elem(xn, sIn, tid + NTHR,   iy0, ix0);
    if (tid + 2 * NTHR < NLD)
        load_tile_elem(xn, sIn, tid + 2 * NTHR, iy0, ix0);
    __syncthreads();

    const int pw = pw0 + tx;
    const int ph = ph0 + ty;
    if (pw >= POW || ph >= POW) return;    // no barriers below

    // 4x4 register patch via conflict-free LDS.64.
    float p[4][4];
    #pragma unroll
    for (int r = 0; r < 4; r++) {
        const float2* row = reinterpret_cast<const float2*>(
            &sIn[2 * ty + r][2 * tx]);
        float2 a = row[0];
        float2 c = row[1];
        p[r][0] = a.x; p[r][1] = a.y; p[r][2] = c.x; p[r][3] = c.y;
    }

    const size_t cstride = (size_t)POW * POW;
    size_t o0 = (((size_t)n * 5) * POW + ph) * POW + pw;

    #pragma unroll
    for (int ch = 0; ch < 5; ch++) {
        const float bias = sB[ch];
        // 4 independent accumulators (2x2 conv positions), updated together.
        float a0 = bias, a1 = bias, a2 = bias, a3 = bias;

        #pragma unroll
        for (int ky = 0; ky < 3; ky++) {
            const float k0 = sW[ch][ky * 3 + 0];
            const float k1 = sW[ch][ky * 3 + 1];
            const float k2 = sW[ch][ky * 3 + 2];
            // position (dy,dx) consumes patch row dy+ky, cols dx..dx+2
            a0 = fmaf(p[ky    ][0], k0, a0);
            a1 = fmaf(p[ky    ][1], k0, a1);
            a2 = fmaf(p[ky + 1][0], k0, a2);
            a3 = fmaf(p[ky + 1][1], k0, a3);
            a0 = fmaf(p[ky    ][1], k1, a0);
            a1 = fmaf(p[ky    ][2], k1, a1);
            a2 = fmaf(p[ky + 1][1], k1, a2);
            a3 = fmaf(p[ky + 1][2], k1, a3);
            a0 = fmaf(p[ky    ][2], k2, a0);
            a1 = fmaf(p[ky    ][3], k2, a1);
            a2 = fmaf(p[ky + 1][2], k2, a2);
            a3 = fmaf(p[ky + 1][3], k2, a3);
        }

        const float m = fmaxf(fmaxf(fmaxf(a0, a1), fmaxf(a2, a3)), 0.0f);
        out[o0] = m;
        o0 += cstride;
    }
}

extern "C" void kernel_launch(void* const* d_in, const int* in_sizes, int n_in,
                              void* d_out, int out_size)
{
    const float* x = (const float*)d_in[0];
    const float* w = (const float*)d_in[1];
    const float* b = (const float*)d_in[2];
    float* out = (float*)d_out;

    dim3 block(TX, TY, 1);                       // 256 threads
    dim3 grid((POW + TX - 1) / TX,               // 8
              (POW + TY - 1) / TY,               // 32
              64);                               // batch
    fused_conv_bias_pool_relu<<<grid, block>>>(x, w, b, out);
}

// round 8
// speedup vs baseline: 1.6748x; 1.0011x over previous
#include <cuda_runtime.h>
#include <cstdint>

// x: [64,1,512,512] f32; kernels: [5,1,3,3]; biases: [5]
// conv VALID -> [64,5,510,510]; +bias; maxpool2x2 -> [64,5,255,255]; relu.
//
// Measured model (R3-R5): issue-slot bound, dur ~ warp_instrs/(592*issue_eff).
// This round: raise occupancy (36-reg cap -> 56 warps/SM) and expose ILP=4
// in the conv accumulation. One pooled output per thread (R3 layout).

#define TX 32
#define TY 8
#define NTHR (TX * TY)
#define IW 66              // 2*TX + 2 tile floats per row
#define IW2 33             // float2 per tile row
#define IH 18              // 2*TY + 2
#define INW 512
#define POW 255
#define NLD (IH * IW2)     // 594

__device__ __forceinline__ void load_tile_elem(const float* __restrict__ xn,
                                               float (*sIn)[IW],
                                               int i, int iy0, int ix0)
{
    const int r  = i / IW2;
    const int c2 = i - r * IW2;
    const int gy = iy0 + r;
    const int gx = ix0 + 2 * c2;
    float2 v;
    if (gy < INW && gx + 1 < INW) {
        v = *reinterpret_cast<const float2*>(xn + (size_t)gy * INW + gx);
    } else {
        v.x = (gy < INW && gx < INW) ? xn[(size_t)gy * INW + gx] : 0.0f;
        v.y = 0.0f;
    }
    sIn[r][2 * c2]     = v.x;
    sIn[r][2 * c2 + 1] = v.y;
}

__global__ __launch_bounds__(NTHR, 7)
void fused_conv_bias_pool_relu(const float* __restrict__ x,
                               const float* __restrict__ w,
                               const float* __restrict__ b,
                               float* __restrict__ out)
{
    __shared__ float sIn[IH][IW];
    __shared__ float sW[5][9];
    __shared__ float sB[5];

    const int n   = blockIdx.z;
    const int pw0 = blockIdx.x * TX;
    const int ph0 = blockIdx.y * TY;
    const int tx  = threadIdx.x;
    const int ty  = threadIdx.y;
    const int tid = ty * TX + tx;

    if (tid < 45)      sW[tid / 9][tid % 9] = w[tid];
    else if (tid < 50) sB[tid - 45] = b[tid - 45];

    // Cooperative float2 load of the 66x18 tile (clamp -> 0 pad).
    // 594 loads / 256 threads: 2 unconditional + 1 masked (peeled for MLP).
    const float* __restrict__ xn = x + (size_t)n * INW * INW;
    const int ix0 = 2 * pw0;               // even
    const int iy0 = 2 * ph0;
    load_tile_elem(xn, sIn, tid,          iy0, ix0);
    load_tile_elem(xn, sIn, tid + NTHR,   iy0, ix0);
    if (tid + 2 * NTHR < NLD)
        load_tile_elem(xn, sIn, tid + 2 * NTHR, iy0, ix0);
    __syncthreads();

    const int pw = pw0 + tx;
    const int ph = ph0 + ty;
    if (pw >= POW || ph >= POW) return;    // no barriers below

    // 4x4 register patch via conflict-free LDS.64.
    float p[4][4];
    #pragma unroll
    for (int r = 0; r < 4; r++) {
        const float2* row = reinterpret_cast<const float2*>(
            &sIn[2 * ty + r][2 * tx]);
        float2 a = row[0];
        float2 c = row[1];
        p[r][0] = a.x; p[r][1] = a.y; p[r][2] = c.x; p[r][3] = c.y;
    }

    const size_t cstride = (size_t)POW * POW;
    size_t o0 = (((size_t)n * 5) * POW + ph) * POW + pw;

    #pragma unroll
    for (int ch = 0; ch < 5; ch++) {
        const float bias = sB[ch];
        // 4 independent accumulators (2x2 conv positions), updated together.
        float a0 = bias, a1 = bias, a2 = bias, a3 = bias;

        #pragma unroll
        for (int ky = 0; ky < 3; ky++) {
            const float k0 = sW[ch][ky * 3 + 0];
            const float k1 = sW[ch][ky * 3 + 1];
            const float k2 = sW[ch][ky * 3 + 2];
            // position (dy,dx) consumes patch row dy+ky, cols dx..dx+2
            a0 = fmaf(p[ky    ][0], k0, a0);
            a1 = fmaf(p[ky    ][1], k0, a1);
            a2 = fmaf(p[ky + 1][0], k0, a2);
            a3 = fmaf(p[ky + 1][1], k0, a3);
            a0 = fmaf(p[ky    ][1], k1, a0);
            a1 = fmaf(p[ky    ][2], k1, a1);
            a2 = fmaf(p[ky + 1][1], k1, a2);
            a3 = fmaf(p[ky + 1][2], k1, a3);
            a0 = fmaf(p[ky    ][2], k2, a0);
            a1 = fmaf(p[ky    ][3], k2, a1);
            a2 = fmaf(p[ky + 1][2], k2, a2);
            a3 = fmaf(p[ky + 1][3], k2, a3);
        }

        const float m = fmaxf(fmaxf(fmaxf(a0, a1), fmaxf(a2, a3)), 0.0f);
        out[o0] = m;
        o0 += cstride;
    }
}

extern "C" void kernel_launch(void* const* d_in, const int* in_sizes, int n_in,
                              void* d_out, int out_size)
{
    const float* x = (const float*)d_in[0];
    const float* w = (const float*)d_in[1];
    const float* b = (const float*)d_in[2];
    float* out = (float*)d_out;

    dim3 block(TX, TY, 1);                       // 256 threads
    dim3 grid((POW + TX - 1) / TX,               // 8
              (POW + TY - 1) / TY,               // 32
              64);                               // batch
    fused_conv_bias_pool_relu<<<grid, block>>>(x, w, b, out);
}

// round 10
// speedup vs baseline: 1.7297x; 1.0328x over previous
#include <cuda_runtime.h>
#include <cstdint>

// x: [64,1,512,512] f32; kernels: [5,1,3,3]; biases: [5]
// conv VALID -> [64,5,510,510]; +bias; maxpool2x2 -> [64,5,255,255]; relu.
//
// Model (R3-R6): FFMA-pipe floor ~44us; excess is issue slots + latency.
// This round: weights+bias as float4 rows {k0,k1,k2,bias|0} -> 3 LDS.128
// per channel (15 total vs 50 scalar LDS). 36-reg cap, ILP-4 kept.

#define TX 32
#define TY 8
#define NTHR (TX * TY)
#define IW 66              // 2*TX + 2 tile floats per row
#define IW2 33             // float2 per tile row
#define IH 18              // 2*TY + 2
#define INW 512
#define POW 255
#define NLD (IH * IW2)     // 594

__device__ __forceinline__ void load_tile_elem(const float* __restrict__ xn,
                                               float (*sIn)[IW],
                                               int i, int iy0, int ix0)
{
    const int r  = i / IW2;
    const int c2 = i - r * IW2;
    const int gy = iy0 + r;
    const int gx = ix0 + 2 * c2;
    float2 v;
    if (gy < INW && gx + 1 < INW) {
        v = *reinterpret_cast<const float2*>(xn + (size_t)gy * INW + gx);
    } else {
        v.x = (gy < INW && gx < INW) ? xn[(size_t)gy * INW + gx] : 0.0f;
        v.y = 0.0f;
    }
    sIn[r][2 * c2]     = v.x;
    sIn[r][2 * c2 + 1] = v.y;
}

__global__ __launch_bounds__(NTHR, 7)
void fused_conv_bias_pool_relu(const float* __restrict__ x,
                               const float* __restrict__ w,
                               const float* __restrict__ b,
                               float* __restrict__ out)
{
    __shared__ float sIn[IH][IW];
    __shared__ float4 sW4[5][3];   // row ky: {k0,k1,k2, ky==0 ? bias : 0}

    const int n   = blockIdx.z;
    const int pw0 = blockIdx.x * TX;
    const int ph0 = blockIdx.y * TY;
    const int tx  = threadIdx.x;
    const int ty  = threadIdx.y;
    const int tid = ty * TX + tx;

    if (tid < 15) {
        const int ch = tid / 3;
        const int ky = tid - ch * 3;
        const float* wr = w + ch * 9 + ky * 3;
        sW4[ch][ky] = make_float4(wr[0], wr[1], wr[2],
                                  (ky == 0) ? b[ch] : 0.0f);
    }

    // Cooperative float2 load of the 66x18 tile (clamp -> 0 pad).
    // 594 loads / 256 threads: 2 unconditional + 1 masked (peeled for MLP).
    const float* __restrict__ xn = x + (size_t)n * INW * INW;
    const int ix0 = 2 * pw0;               // even
    const int iy0 = 2 * ph0;
    load_tile_elem(xn, sIn, tid,          iy0, ix0);
    load_tile_elem(xn, sIn, tid + NTHR,   iy0, ix0);
    if (tid + 2 * NTHR < NLD)
        load_tile_elem(xn, sIn, tid + 2 * NTHR, iy0, ix0);
    __syncthreads();

    const int pw = pw0 + tx;
    const int ph = ph0 + ty;
    if (pw >= POW || ph >= POW) return;    // no barriers below

    // 4x4 register patch via conflict-free LDS.64.
    float p[4][4];
    #pragma unroll
    for (int r = 0; r < 4; r++) {
        const float2* row = reinterpret_cast<const float2*>(
            &sIn[2 * ty + r][2 * tx]);
        float2 a = row[0];
        float2 c = row[1];
        p[r][0] = a.x; p[r][1] = a.y; p[r][2] = c.x; p[r][3] = c.y;
    }

    // 32-bit output addressing (64*5*255*255 < 2^31).
    const int cstride = POW * POW;
    int o0 = ((n * 5) * POW + ph) * POW + pw;

    #pragma unroll
    for (int ch = 0; ch < 5; ch++) {
        // ky = 0 row carries bias in .w -> initializes all 4 accumulators.
        float4 kr = sW4[ch][0];
        float a0 = kr.w, a1 = kr.w, a2 = kr.w, a3 = kr.w;

        #pragma unroll
        for (int ky = 0; ky < 3; ky++) {
            if (ky > 0) kr = sW4[ch][ky];
            // position (dy,dx) consumes patch row dy+ky, cols dx..dx+2
            a0 = fmaf(p[ky    ][0], kr.x, a0);
            a1 = fmaf(p[ky    ][1], kr.x, a1);
            a2 = fmaf(p[ky + 1][0], kr.x, a2);
            a3 = fmaf(p[ky + 1][1], kr.x, a3);
            a0 = fmaf(p[ky    ][1], kr.y, a0);
            a1 = fmaf(p[ky    ][2], kr.y, a1);
            a2 = fmaf(p[ky + 1][1], kr.y, a2);
            a3 = fmaf(p[ky + 1][2], kr.y, a3);
            a0 = fmaf(p[ky    ][2], kr.z, a0);
            a1 = fmaf(p[ky    ][3], kr.z, a1);
            a2 = fmaf(p[ky + 1][2], kr.z, a2);
            a3 = fmaf(p[ky + 1][3], kr.z, a3);
        }

        const float m = fmaxf(fmaxf(fmaxf(a0, a1), fmaxf(a2, a3)), 0.0f);
        out[o0] = m;
        o0 += cstride;
    }
}

extern "C" void kernel_launch(void* const* d_in, const int* in_sizes, int n_in,
                              void* d_out, int out_size)
{
    const float* x = (const float*)d_in[0];
    const float* w = (const float*)d_in[1];
    const float* b = (const float*)d_in[2];
    float* out = (float*)d_out;

    dim3 block(TX, TY, 1);                       // 256 threads
    dim3 grid((POW + TX - 1) / TX,               // 8
              (POW + TY - 1) / TY,               // 32
              64);                               // batch
    fused_conv_bias_pool_relu<<<grid, block>>>(x, w, b, out);
}

// round 11
// speedup vs baseline: 2.0120x; 1.1632x over previous
#include <cuda_runtime.h>
#include <cstdint>

// x: [64,1,512,512] f32; kernels: [5,1,3,3]; biases: [5]
// conv VALID -> [64,5,510,510]; +bias; maxpool2x2 -> [64,5,255,255]; relu.
//
// Model (R3-R10): FFMA rt=2 issue cap => ~44us floor; at 55.6us we were at
// 88% of that cap. This round deletes the shared input tile (all patch
// coords provably in-bounds): 8 direct LDG.64 per thread, halo served by
// L1/L2. Removes tile-load arithmetic, STS, LDS and the main barrier.

#define TX 32
#define TY 8
#define NTHR (TX * TY)
#define INW 512
#define POW 255

__global__ __launch_bounds__(NTHR, 8)
void fused_conv_bias_pool_relu(const float* __restrict__ x,
                               const float* __restrict__ w,
                               const float* __restrict__ b,
                               float* __restrict__ out)
{
    __shared__ float4 sW4[5][3];   // row ky: {k0,k1,k2, ky==0 ? bias : 0}

    const int tx  = threadIdx.x;
    const int ty  = threadIdx.y;
    const int tid = ty * TX + tx;

    if (tid < 15) {
        const int ch = tid / 3;
        const int ky = tid - ch * 3;
        const float* wr = w + ch * 9 + ky * 3;
        sW4[ch][ky] = make_float4(wr[0], wr[1], wr[2],
                                  (ky == 0) ? b[ch] : 0.0f);
    }
    __syncthreads();   // weights only; all threads participate, then mask

    const int n  = blockIdx.z;
    const int pw = blockIdx.x * TX + tx;   // 0..255
    const int ph = blockIdx.y * TY + ty;   // 0..255
    if (pw >= POW || ph >= POW) return;

    // Direct global loads of the 4x4 patch. Rows 2ph..2ph+3 <= 511 and
    // cols 2pw..2pw+3 <= 511 are always in-bounds. 8 x LDG.64, MLP=8.
    const float* __restrict__ px =
        x + ((size_t)n * INW + (size_t)(2 * ph)) * INW + 2 * pw;
    float2 r0a = *reinterpret_cast<const float2*>(px);
    float2 r0b = *reinterpret_cast<const float2*>(px + 2);
    float2 r1a = *reinterpret_cast<const float2*>(px + INW);
    float2 r1b = *reinterpret_cast<const float2*>(px + INW + 2);
    float2 r2a = *reinterpret_cast<const float2*>(px + 2 * INW);
    float2 r2b = *reinterpret_cast<const float2*>(px + 2 * INW + 2);
    float2 r3a = *reinterpret_cast<const float2*>(px + 3 * INW);
    float2 r3b = *reinterpret_cast<const float2*>(px + 3 * INW + 2);

    float p[4][4];
    p[0][0] = r0a.x; p[0][1] = r0a.y; p[0][2] = r0b.x; p[0][3] = r0b.y;
    p[1][0] = r1a.x; p[1][1] = r1a.y; p[1][2] = r1b.x; p[1][3] = r1b.y;
    p[2][0] = r2a.x; p[2][1] = r2a.y; p[2][2] = r2b.x; p[2][3] = r2b.y;
    p[3][0] = r3a.x; p[3][1] = r3a.y; p[3][2] = r3b.x; p[3][3] = r3b.y;

    // 32-bit output addressing (64*5*255*255 < 2^31).
    const int cstride = POW * POW;
    int o0 = ((n * 5) * POW + ph) * POW + pw;

    #pragma unroll
    for (int ch = 0; ch < 5; ch++) {
        // ky = 0 row carries bias in .w -> initializes all 4 accumulators.
        float4 kr = sW4[ch][0];
        float a0 = kr.w, a1 = kr.w, a2 = kr.w, a3 = kr.w;

        #pragma unroll
        for (int ky = 0; ky < 3; ky++) {
            if (ky > 0) kr = sW4[ch][ky];
            a0 = fmaf(p[ky    ][0], kr.x, a0);
            a1 = fmaf(p[ky    ][1], kr.x, a1);
            a2 = fmaf(p[ky + 1][0], kr.x, a2);
            a3 = fmaf(p[ky + 1][1], kr.x, a3);
            a0 = fmaf(p[ky    ][1], kr.y, a0);
            a1 = fmaf(p[ky    ][2], kr.y, a1);
            a2 = fmaf(p[ky + 1][1], kr.y, a2);
            a3 = fmaf(p[ky + 1][2], kr.y, a3);
            a0 = fmaf(p[ky    ][2], kr.z, a0);
            a1 = fmaf(p[ky    ][3], kr.z, a1);
            a2 = fmaf(p[ky + 1][2], kr.z, a2);
            a3 = fmaf(p[ky + 1][3], kr.z, a3);
        }

        const float m = fmaxf(fmaxf(fmaxf(a0, a1), fmaxf(a2, a3)), 0.0f);
        out[o0] = m;
        o0 += cstride;
    }
}

extern "C" void kernel_launch(void* const* d_in, const int* in_sizes, int n_in,
                              void* d_out, int out_size)
{
    const float* x = (const float*)d_in[0];
    const float* w = (const float*)d_in[1];
    const float* b = (const float*)d_in[2];
    float* out = (float*)d_out;

    dim3 block(TX, TY, 1);                       // 256 threads
    dim3 grid((POW + TX - 1) / TX,               // 8
              (POW + TY - 1) / TY,               // 32
              64);                               // batch
    fused_conv_bias_pool_relu<<<grid, block>>>(x, w, b, out);
}